// round 2
// baseline (speedup 1.0000x reference)
#include <cuda_runtime.h>
#include <cstdint>

// ---------------------------------------------------------------------------
// params computed on device by the prologue kernel: {p_off, p_diag}
// ---------------------------------------------------------------------------
__device__ float g_params[2];

__global__ void abar_kernel(const float* __restrict__ beta,
                            const int* __restrict__ t_ptr) {
    int t = *t_ptr;
    int lane = threadIdx.x;  // 32 threads
    float prod = 1.0f;
    for (int i = lane; i < t; i += 32) prod *= (1.0f - beta[i]);
#pragma unroll
    for (int d = 16; d > 0; d >>= 1)
        prod *= __shfl_xor_sync(0xFFFFFFFFu, prod, d);
    if (lane == 0) {
        float abar = prod;
        float p_off = (1.0f - abar) * (1.0f / 256.0f);  // (1-abar)/K
        float p_diag = abar + p_off;                    // abar + (1-abar)/K
        g_params[0] = p_off;
        g_params[1] = p_diag;
    }
}

// ---------------------------------------------------------------------------
// threefry2x32, 20 rounds, key = (0, 1)  (jax.random.key(1))
// Partitionable layout: element i -> counter (hi, lo) = (0, i); 32-bit output
// is o0 ^ o1.
// ---------------------------------------------------------------------------
__device__ __forceinline__ uint32_t rotl32(uint32_t x, int d) {
    return __funnelshift_l(x, x, d);
}

__device__ __forceinline__ uint32_t threefry01_xor(uint32_t c1) {
    const uint32_t ks0 = 0u;
    const uint32_t ks1 = 1u;
    const uint32_t ks2 = 0x1BD11BDBu;  // 0x1BD11BDA ^ 0 ^ 1
    uint32_t x0 = 0u + ks0;            // counter hi = 0 always
    uint32_t x1 = c1 + ks1;
#define TF_RND(R) { x0 += x1; x1 = rotl32(x1, R); x1 ^= x0; }
    TF_RND(13) TF_RND(15) TF_RND(26) TF_RND(6)
    x0 += ks1; x1 += ks2 + 1u;
    TF_RND(17) TF_RND(29) TF_RND(16) TF_RND(24)
    x0 += ks2; x1 += ks0 + 2u;
    TF_RND(13) TF_RND(15) TF_RND(26) TF_RND(6)
    x0 += ks0; x1 += ks1 + 3u;
    TF_RND(17) TF_RND(29) TF_RND(16) TF_RND(24)
    x0 += ks1; x1 += ks2 + 4u;
    TF_RND(13) TF_RND(15) TF_RND(26) TF_RND(6)
    x0 += ks2; x1 += ks0 + 5u;
#undef TF_RND
    return x0 ^ x1;
}

// jax uniform: f = bitcast((bits>>9)|0x3F800000) - 1 ; u ~= max(1e-9, f + 1e-9)
__device__ __forceinline__ float bits_to_u(uint32_t b) {
    float f = __uint_as_float((b >> 9) | 0x3F800000u) - 1.0f;
    return fmaxf(1e-9f, f + 1e-9f);
}

// Accurate -ln(u) for u in [1e-9, 1). Cephes logf polynomial; relative
// accuracy preserved as u -> 1 (x = m-1 exact, corrections O(x^2)).
__device__ __forceinline__ float neg_log_accurate(float u) {
    int ib = __float_as_int(u);
    int e = (ib >> 23) - 126;  // u = m * 2^e, m in [0.5, 1)
    float m = __int_as_float((ib & 0x007FFFFF) | 0x3F000000);
    if (m < 0.70710678f) { m = m + m; e -= 1; }
    float x = m - 1.0f;  // in [-0.2929, 0.4142], exact
    float z = x * x;
    float p =            7.0376836292e-2f;
    p = fmaf(p, x, -1.1514610310e-1f);
    p = fmaf(p, x,  1.1676998740e-1f);
    p = fmaf(p, x, -1.2420140846e-1f);
    p = fmaf(p, x,  1.4249322787e-1f);
    p = fmaf(p, x, -1.6668057665e-1f);
    p = fmaf(p, x,  2.0000714765e-1f);
    p = fmaf(p, x, -2.4999993993e-1f);
    p = fmaf(p, x,  3.3333331174e-1f);
    float y = p * (z * x);
    float fe = (float)e;
    y = fmaf(fe, -2.12194440e-4f, y);
    y = fmaf(-0.5f, z, y);
    float ln = x + y;
    ln = fmaf(fe, 0.693359375f, ln);
    return -ln;
}

// ---------------------------------------------------------------------------
// Main kernel: one warp per pixel. 256 channels -> 8 per lane (2x float4).
// Element linear index i = pixel*256 + channel, i < 2^25.
// ---------------------------------------------------------------------------
__global__ __launch_bounds__(256)
void gumbel_softmax_kernel(const float4* __restrict__ x0,
                           float4* __restrict__ out) {
    const int pixel = (blockIdx.x * blockDim.x + threadIdx.x) >> 5;  // [0,131072)
    const int lane = threadIdx.x & 31;

    const float p_off  = g_params[0];
    const float p_diag = g_params[1];

    float w[8];
    float s = 0.0f;

#pragma unroll
    for (int half = 0; half < 2; half++) {
        const int vecIdx = lane + half * 32;          // float4 index in pixel
        float4 a = x0[pixel * 64 + vecIdx];
        float av[4] = {a.x, a.y, a.z, a.w};
        const uint32_t ibase = ((uint32_t)pixel << 8) + ((uint32_t)vecIdx << 2);
#pragma unroll
        for (int c = 0; c < 4; c++) {
            uint32_t bits = threefry01_xor(ibase + (uint32_t)c);
            float e = neg_log_accurate(bits_to_u(bits));
            float pv = (av[c] != 0.0f) ? p_diag : p_off;
            float wv = __fdividef(pv, e);
            w[half * 4 + c] = wv;
            s += wv;
        }
    }

#pragma unroll
    for (int d = 16; d > 0; d >>= 1)
        s += __shfl_xor_sync(0xFFFFFFFFu, s, d);
    const float inv = __fdividef(1.0f, s);

#pragma unroll
    for (int half = 0; half < 2; half++) {
        const int vecIdx = lane + half * 32;
        float4 o;
        o.x = w[half * 4 + 0] * inv;
        o.y = w[half * 4 + 1] * inv;
        o.z = w[half * 4 + 2] * inv;
        o.w = w[half * 4 + 3] * inv;
        out[pixel * 64 + vecIdx] = o;
    }
}

// ---------------------------------------------------------------------------
extern "C" void kernel_launch(void* const* d_in, const int* in_sizes, int n_in,
                              void* d_out, int out_size) {
    const float* x0   = (const float*)d_in[0];
    const float* beta = (const float*)d_in[1];
    const int*   t    = (const int*)d_in[2];
    float* out = (float*)d_out;

    abar_kernel<<<1, 32>>>(beta, t);
    // 131072 pixels -> 131072 warps -> 16384 blocks of 256 threads
    gumbel_softmax_kernel<<<16384, 256>>>((const float4*)x0, (float4*)out);
}